// round 1
// baseline (speedup 1.0000x reference)
#include <cuda_runtime.h>

// ---------------------------------------------------------------------------
// SplatterPhongShader: N=4, H=256, W=256, K=4
// Pass 1: elementwise Phong shade + separable splat-weight factors -> scratch
// Pass 2: 3x3 gather with depth-occlusion bucketing + compositing -> d_out
// ---------------------------------------------------------------------------

namespace cfg {
constexpr int NB = 4, HH = 256, WW = 256, KK = 4;
constexpr int NE   = NB * HH * WW * KK;   // 1,048,576 source elements
constexpr int NPIX = NB * HH * WW;        // 262,144 output pixels
// (1+0.05) / (1 + 4*exp(-2) + 4*exp(-4))
constexpr float NORM_C = 0.6503143832f;
}

// Scratch (36 MB total): per element rgb[3], fy[3] (norm_c*alpha folded), fx[3]
__device__ float4 g_bufA[cfg::NE];   // (rgb.x, rgb.y, rgb.z, fx0)
__device__ float4 g_bufB[cfg::NE];   // (fy0, fy1, fy2, fx1)
__device__ float  g_bufC[cfg::NE];   // fx2
__device__ int    g_mask_kind;       // 0=int32, 1=float32, 2=byte/bool

// ---------------------------------------------------------------------------
// Mask dtype probe. Scans the first 16384 32-bit words (= 65536 bytes, safe
// under every candidate layout since the mask has 1,048,576 elements).
//   int32 mask:  every word is 0 or 1
//   float mask:  every word is 0 or 0x3f800000
//   bool mask:   bytes are 0/1 with cumsum monotonicity per 4-byte group, so
//                nonzero words look like 0x01000000 / 0x01010101 etc (never 1)
// ---------------------------------------------------------------------------
__global__ void detect_kernel(const unsigned int* __restrict__ mw) {
    __shared__ unsigned int sflag[2];
    if (threadIdx.x == 0) { sflag[0] = 0u; sflag[1] = 0u; }
    __syncthreads();
    unsigned int not01 = 0u, notfp = 0u;
    for (int i = threadIdx.x; i < 16384; i += blockDim.x) {
        unsigned int w = mw[i];
        if (w > 1u) not01 = 1u;
        if (w != 0u && w != 0x3f800000u) notfp = 1u;
    }
    if (not01) atomicOr(&sflag[0], 1u);
    if (notfp) atomicOr(&sflag[1], 1u);
    __syncthreads();
    if (threadIdx.x == 0) {
        g_mask_kind = (sflag[0] == 0u) ? 0 : ((sflag[1] == 0u) ? 1 : 2);
    }
}

// ---------------------------------------------------------------------------
// Pass 1: Phong shading + separable gaussian factors
// ---------------------------------------------------------------------------
__global__ __launch_bounds__(256)
void shade_kernel(const float* __restrict__ texels,
                  const float* __restrict__ normals,
                  const float* __restrict__ pcam,
                  const float* __restrict__ screen,
                  const void*  __restrict__ mask,
                  const float* __restrict__ Lp,  // light_position
                  const float* __restrict__ la,
                  const float* __restrict__ ld,
                  const float* __restrict__ ls,
                  const float* __restrict__ Cp,  // camera_position
                  const float* __restrict__ ma,
                  const float* __restrict__ md,
                  const float* __restrict__ ms)
{
    const int e = blockIdx.x * blockDim.x + threadIdx.x;
    if (e >= cfg::NE) return;

    const int x = (e >> 2)  & 255;
    const int y = (e >> 10) & 255;

    // ---- mask -> alpha (exact 0/1) ----
    const int kind = g_mask_kind;
    bool m;
    if (kind == 0)      m = (((const int*)mask)[e] != 0);
    else if (kind == 1) m = (((const float*)mask)[e] != 0.0f);
    else                m = (((const unsigned char*)mask)[e] != 0);
    const float alpha = m ? 0.0f : 1.0f;

    // ---- Phong ----
    const float t0 = texels[3*e+0], t1 = texels[3*e+1], t2 = texels[3*e+2];
    float nx = normals[3*e+0], ny = normals[3*e+1], nz = normals[3*e+2];
    const float px = pcam[3*e+0], py = pcam[3*e+1], pz = pcam[3*e+2];

    float rin = rsqrtf(nx*nx + ny*ny + nz*nz + 1e-8f);
    nx *= rin; ny *= rin; nz *= rin;

    float lx = Lp[0] - px, ly = Lp[1] - py, lz = Lp[2] - pz;
    float ril = rsqrtf(lx*lx + ly*ly + lz*lz + 1e-8f);
    lx *= ril; ly *= ril; lz *= ril;

    float vx = Cp[0] - px, vy = Cp[1] - py, vz = Cp[2] - pz;
    float riv = rsqrtf(vx*vx + vy*vy + vz*vz + 1e-8f);
    vx *= riv; vy *= riv; vz *= riv;

    const float ndl = nx*lx + ny*ly + nz*lz;
    const float two_ndl = 2.0f * ndl;
    const float rx = two_ndl*nx - lx;
    const float ry = two_ndl*ny - ly;
    const float rz = two_ndl*nz - lz;
    float rdv = fmaxf(rx*vx + ry*vy + rz*vz, 0.0f);

    // rdv^64 by repeated squaring
    float s = rdv*rdv;  s = s*s;  s = s*s;  s = s*s;  s = s*s;  s = s*s;

    const float relndl = fmaxf(ndl, 0.0f);
    const float rgb0 = t0 * (la[0]*ma[0] + ld[0]*md[0]*relndl) + ls[0]*ms[0]*s;
    const float rgb1 = t1 * (la[1]*ma[1] + ld[1]*md[1]*relndl) + ls[1]*ms[1]*s;
    const float rgb2 = t2 * (la[2]*ma[2] + ld[2]*md[2]*relndl) + ls[2]*ms[2]*s;

    // ---- separable gaussian splat factors ----
    // jitter = screen coord - own pixel center
    const float jy = screen[2*e+0] - ((float)y + 0.5f);
    const float jx = screen[2*e+1] - ((float)x + 0.5f);
    const float na = cfg::NORM_C * alpha;

    // fy[i] = exp(-(jy-(i-1))^2 / (2*sigma^2)),  2*sigma^2 = 0.5 -> * 2.0
    const float fy0 = __expf(-2.0f * (jy + 1.0f) * (jy + 1.0f)) * na;
    const float fy1 = __expf(-2.0f *  jy         *  jy        ) * na;
    const float fy2 = __expf(-2.0f * (jy - 1.0f) * (jy - 1.0f)) * na;
    const float fx0 = __expf(-2.0f * (jx + 1.0f) * (jx + 1.0f));
    const float fx1 = __expf(-2.0f *  jx         *  jx        );
    const float fx2 = __expf(-2.0f * (jx - 1.0f) * (jx - 1.0f));

    g_bufA[e] = make_float4(rgb0, rgb1, rgb2, fx0);
    g_bufB[e] = make_float4(fy0, fy1, fy2, fx1);
    g_bufC[e] = fx2;
}

// ---------------------------------------------------------------------------
// Pass 2: gather 3x3 neighborhood, depth-occlusion bucketing, composite
// ---------------------------------------------------------------------------
__global__ __launch_bounds__(128)
void blend_kernel(const float* __restrict__ qdepth, float* __restrict__ out)
{
    const int x = blockIdx.x * 32 + threadIdx.x;
    const int y = blockIdx.y * blockDim.y + threadIdx.y;
    const int n = blockIdx.z;
    const int pix = (n * cfg::HH + y) * cfg::WW + x;

    const float4* __restrict__ q4 = reinterpret_cast<const float4*>(qdepth);
    const float4 q = q4[pix];
    const float q0 = q.x;

    float accF[4] = {0.f, 0.f, 0.f, 0.f};   // level < 0  (foreground)
    float accS[4] = {0.f, 0.f, 0.f, 0.f};   // level == 0 (surface)
    float accB[4] = {0.f, 0.f, 0.f, 0.f};   // level > 0  (background)

#pragma unroll
    for (int d = 0; d < 9; ++d) {
        const int dy = d / 3 - 1;
        const int dx = d % 3 - 1;
        const int sy = y - dy;
        const int sx = x - dx;
        if ((unsigned)sy >= (unsigned)cfg::HH || (unsigned)sx >= (unsigned)cfg::WW)
            continue;
        const int spix = (n * cfg::HH + sy) * cfg::WW + sx;
        const float4 pq = q4[spix];
        const float ptop = pq.x;

        // lq / dq_min: which of OWN layers is closest to neighbor's top depth
        float dqm = fabsf(ptop - q.x); int lq = 0;
        { float a = fabsf(ptop - q.y); if (a < dqm) { dqm = a; lq = 1; } }
        { float a = fabsf(ptop - q.z); if (a < dqm) { dqm = a; lq = 2; } }
        { float a = fabsf(ptop - q.w); if (a < dqm) { dqm = a; lq = 3; } }

        // lp / dp_min: which of NEIGHBOR layers is closest to own top depth
        float dpm = fabsf(q0 - pq.x); int lp = 0;
        { float a = fabsf(q0 - pq.y); if (a < dpm) { dpm = a; lp = 1; } }
        { float a = fabsf(q0 - pq.z); if (a < dpm) { dpm = a; lp = 2; } }
        { float a = fabsf(q0 - pq.w); if (a < dpm) { dpm = a; lp = 3; } }

        const int occ = (dqm <= dpm) ? lq : -lp;
        const int base = spix * cfg::KK;

#pragma unroll
        for (int kk = 0; kk < cfg::KK; ++kk) {
            const float4 A = g_bufA[base + kk];
            const float4 B = g_bufB[base + kk];
            const float fyv = (dy == -1) ? B.x : ((dy == 0) ? B.y : B.z);
            const float fxv = (dx == -1) ? A.w : ((dx == 0) ? B.w : g_bufC[base + kk]);
            const float w = fyv * fxv;
            const int lvl = kk + occ;
            if (lvl < 0) {
                accF[0] = fmaf(A.x, w, accF[0]);
                accF[1] = fmaf(A.y, w, accF[1]);
                accF[2] = fmaf(A.z, w, accF[2]);
                accF[3] += w;
            } else if (lvl == 0) {
                accS[0] = fmaf(A.x, w, accS[0]);
                accS[1] = fmaf(A.y, w, accS[1]);
                accS[2] = fmaf(A.z, w, accS[2]);
                accS[3] += w;
            } else {
                accB[0] = fmaf(A.x, w, accB[0]);
                accB[1] = fmaf(A.y, w, accB[1]);
                accB[2] = fmaf(A.z, w, accB[2]);
                accB[3] += w;
            }
        }
    }

    // normalize each bucket (alpha channel == weight channel, see analysis)
    const float ib = 1.0f / fmaxf(accB[3], 1e-10f);
    float o0 = accB[0] * ib, o1 = accB[1] * ib, o2 = accB[2] * ib, o3 = accB[3] * ib;

    const float is = 1.0f / fmaxf(accS[3], 1e-10f);
    {
        const float s0 = accS[0]*is, s1 = accS[1]*is, s2 = accS[2]*is, s3 = accS[3]*is;
        const float om = 1.0f - s3;
        o0 = s0 + om * o0; o1 = s1 + om * o1; o2 = s2 + om * o2; o3 = s3 + om * o3;
    }
    const float iff = 1.0f / fmaxf(accF[3], 1e-10f);
    {
        const float f0 = accF[0]*iff, f1 = accF[1]*iff, f2 = accF[2]*iff, f3 = accF[3]*iff;
        const float om = 1.0f - f3;
        o0 = f0 + om * o0; o1 = f1 + om * o1; o2 = f2 + om * o2; o3 = f3 + om * o3;
    }

    // blend with white background
    const float bgm = 1.0f - o3;
    reinterpret_cast<float4*>(out)[pix] =
        make_float4(o0 + bgm, o1 + bgm, o2 + bgm, o3);
}

// ---------------------------------------------------------------------------
extern "C" void kernel_launch(void* const* d_in, const int* in_sizes, int n_in,
                              void* d_out, int out_size)
{
    const float* texels  = (const float*)d_in[0];
    const float* normals = (const float*)d_in[1];
    const float* pcam    = (const float*)d_in[2];
    const float* screen  = (const float*)d_in[3];
    const float* qdepth  = (const float*)d_in[4];
    const void*  mask    = d_in[5];
    const float* Lp      = (const float*)d_in[6];
    const float* la      = (const float*)d_in[7];
    const float* ld      = (const float*)d_in[8];
    const float* ls      = (const float*)d_in[9];
    const float* Cp      = (const float*)d_in[10];
    const float* ma      = (const float*)d_in[11];
    const float* md      = (const float*)d_in[12];
    const float* ms      = (const float*)d_in[13];
    float* out = (float*)d_out;

    detect_kernel<<<1, 256>>>((const unsigned int*)mask);

    shade_kernel<<<cfg::NE / 256, 256>>>(texels, normals, pcam, screen, mask,
                                         Lp, la, ld, ls, Cp, ma, md, ms);

    dim3 blk(32, 4, 1);
    dim3 grd(cfg::WW / 32, cfg::HH / 4, cfg::NB);
    blend_kernel<<<grd, blk>>>(qdepth, out);
}

// round 2
// speedup vs baseline: 1.6497x; 1.6497x over previous
#include <cuda_runtime.h>

// ---------------------------------------------------------------------------
// SplatterPhongShader: N=4, H=256, W=256, K=4
// Pass 1: elementwise Phong shade + separable splat-weight factors -> scratch
// Pass 2: 3x3 gather with depth-occlusion bucketing + compositing -> d_out
// Scratch is SoA over the K (layer) dimension so blend's per-layer loads are
// fully coalesced (4 L1 wavefronts per warp-LDG.128 instead of 16).
// ---------------------------------------------------------------------------

namespace cfg {
constexpr int NB = 4, HH = 256, WW = 256, KK = 4;
constexpr int NE   = NB * HH * WW * KK;   // 1,048,576 source elements
constexpr int NPIX = NB * HH * WW;        // 262,144 pixels
// (1+0.05) / (1 + 4*exp(-2) + 4*exp(-4))
constexpr float NORM_C = 0.6503143832f;
}

// Scratch, SoA by layer: [kk][pix]
__device__ float4 g_A[cfg::KK][cfg::NPIX];   // (rgb0, rgb1, rgb2, fx0)
__device__ float4 g_B[cfg::KK][cfg::NPIX];   // (fy0, fy1, fy2, fx1)
__device__ float  g_C[cfg::KK][cfg::NPIX];   // fx2
__device__ int    g_mask_kind;               // 0=int32, 1=float32, 2=byte/bool

// ---------------------------------------------------------------------------
// Mask dtype probe (fast version): 1024 threads, 4 independent uint4 each,
// scanning the first 16384 words (64KB; safe under every candidate layout).
//   int32 mask:  every word is 0 or 1
//   float mask:  every word is 0 or 0x3f800000
//   bool mask:   packed bytes -> nonzero words are multi-byte patterns > 1
// ---------------------------------------------------------------------------
__global__ __launch_bounds__(1024)
void detect_kernel(const uint4* __restrict__ mw) {
    __shared__ unsigned int sflag[2];
    if (threadIdx.x == 0) { sflag[0] = 0u; sflag[1] = 0u; }
    __syncthreads();
    unsigned int not01 = 0u, notfp = 0u;
    uint4 v[4];
#pragma unroll
    for (int j = 0; j < 4; ++j) v[j] = mw[threadIdx.x + j * 1024];
#pragma unroll
    for (int j = 0; j < 4; ++j) {
        const unsigned int ws[4] = {v[j].x, v[j].y, v[j].z, v[j].w};
#pragma unroll
        for (int t = 0; t < 4; ++t) {
            unsigned int w = ws[t];
            if (w > 1u) not01 = 1u;
            if (w != 0u && w != 0x3f800000u) notfp = 1u;
        }
    }
    not01 = __ballot_sync(0xffffffffu, not01);
    notfp = __ballot_sync(0xffffffffu, notfp);
    if ((threadIdx.x & 31) == 0) {
        if (not01) atomicOr(&sflag[0], 1u);
        if (notfp) atomicOr(&sflag[1], 1u);
    }
    __syncthreads();
    if (threadIdx.x == 0)
        g_mask_kind = (sflag[0] == 0u) ? 0 : ((sflag[1] == 0u) ? 1 : 2);
}

// ---------------------------------------------------------------------------
// Pass 1: Phong shading + separable gaussian factors
// ---------------------------------------------------------------------------
__global__ __launch_bounds__(256)
void shade_kernel(const float* __restrict__ texels,
                  const float* __restrict__ normals,
                  const float* __restrict__ pcam,
                  const float* __restrict__ screen,
                  const void*  __restrict__ mask,
                  const float* __restrict__ Lp,
                  const float* __restrict__ la,
                  const float* __restrict__ ld,
                  const float* __restrict__ ls,
                  const float* __restrict__ Cp,
                  const float* __restrict__ ma,
                  const float* __restrict__ md,
                  const float* __restrict__ ms)
{
    const int e = blockIdx.x * blockDim.x + threadIdx.x;
    if (e >= cfg::NE) return;

    const int pix = e >> 2;
    const int kk  = e & 3;
    const int x = (e >> 2)  & 255;
    const int y = (e >> 10) & 255;

    // ---- mask -> alpha (exact 0/1) ----
    const int kind = g_mask_kind;
    bool m;
    if (kind == 0)      m = (((const int*)mask)[e] != 0);
    else if (kind == 1) m = (((const float*)mask)[e] != 0.0f);
    else                m = (((const unsigned char*)mask)[e] != 0);
    const float alpha = m ? 0.0f : 1.0f;

    // ---- Phong ----
    const float t0 = texels[3*e+0], t1 = texels[3*e+1], t2 = texels[3*e+2];
    float nx = normals[3*e+0], ny = normals[3*e+1], nz = normals[3*e+2];
    const float px = pcam[3*e+0], py = pcam[3*e+1], pz = pcam[3*e+2];

    float rin = rsqrtf(nx*nx + ny*ny + nz*nz + 1e-8f);
    nx *= rin; ny *= rin; nz *= rin;

    float lx = Lp[0] - px, ly = Lp[1] - py, lz = Lp[2] - pz;
    float ril = rsqrtf(lx*lx + ly*ly + lz*lz + 1e-8f);
    lx *= ril; ly *= ril; lz *= ril;

    float vx = Cp[0] - px, vy = Cp[1] - py, vz = Cp[2] - pz;
    float riv = rsqrtf(vx*vx + vy*vy + vz*vz + 1e-8f);
    vx *= riv; vy *= riv; vz *= riv;

    const float ndl = nx*lx + ny*ly + nz*lz;
    const float two_ndl = 2.0f * ndl;
    const float rx = two_ndl*nx - lx;
    const float ry = two_ndl*ny - ly;
    const float rz = two_ndl*nz - lz;
    float rdv = fmaxf(rx*vx + ry*vy + rz*vz, 0.0f);

    // rdv^64 by repeated squaring
    float s = rdv*rdv;  s = s*s;  s = s*s;  s = s*s;  s = s*s;  s = s*s;

    const float relndl = fmaxf(ndl, 0.0f);
    const float rgb0 = t0 * (la[0]*ma[0] + ld[0]*md[0]*relndl) + ls[0]*ms[0]*s;
    const float rgb1 = t1 * (la[1]*ma[1] + ld[1]*md[1]*relndl) + ls[1]*ms[1]*s;
    const float rgb2 = t2 * (la[2]*ma[2] + ld[2]*md[2]*relndl) + ls[2]*ms[2]*s;

    // ---- separable gaussian splat factors (2*sigma^2 = 0.5 -> coeff 2.0) ----
    const float jy = screen[2*e+0] - ((float)y + 0.5f);
    const float jx = screen[2*e+1] - ((float)x + 0.5f);
    const float na = cfg::NORM_C * alpha;

    const float fy0 = __expf(-2.0f * (jy + 1.0f) * (jy + 1.0f)) * na;
    const float fy1 = __expf(-2.0f *  jy         *  jy        ) * na;
    const float fy2 = __expf(-2.0f * (jy - 1.0f) * (jy - 1.0f)) * na;
    const float fx0 = __expf(-2.0f * (jx + 1.0f) * (jx + 1.0f));
    const float fx1 = __expf(-2.0f *  jx         *  jx        );
    const float fx2 = __expf(-2.0f * (jx - 1.0f) * (jx - 1.0f));

    g_A[kk][pix] = make_float4(rgb0, rgb1, rgb2, fx0);
    g_B[kk][pix] = make_float4(fy0, fy1, fy2, fx1);
    g_C[kk][pix] = fx2;
}

// ---------------------------------------------------------------------------
// Pass 2: gather 3x3 neighborhood, depth-occlusion bucketing, composite
// ---------------------------------------------------------------------------
__global__ __launch_bounds__(256)
void blend_kernel(const float* __restrict__ qdepth, float* __restrict__ out)
{
    const int x = blockIdx.x * 32 + threadIdx.x;
    const int y = blockIdx.y * blockDim.y + threadIdx.y;
    const int n = blockIdx.z;
    const int pix = (n * cfg::HH + y) * cfg::WW + x;

    const float4* __restrict__ q4 = reinterpret_cast<const float4*>(qdepth);
    const float4 q = q4[pix];
    const float q0 = q.x;

    float accF[4] = {0.f, 0.f, 0.f, 0.f};   // level < 0  (foreground)
    float accS[4] = {0.f, 0.f, 0.f, 0.f};   // level == 0 (surface)
    float accB[4] = {0.f, 0.f, 0.f, 0.f};   // level > 0  (background)

#pragma unroll
    for (int d = 0; d < 9; ++d) {
        const int dy = d / 3 - 1;
        const int dx = d % 3 - 1;
        const int sy = y - dy;
        const int sx = x - dx;
        if ((unsigned)sy >= (unsigned)cfg::HH || (unsigned)sx >= (unsigned)cfg::WW)
            continue;
        const int spix = (n * cfg::HH + sy) * cfg::WW + sx;
        const float4 pq = q4[spix];
        const float ptop = pq.x;

        // lq / dq_min: which of OWN layers is closest to neighbor's top depth
        float dqm = fabsf(ptop - q.x); int lq = 0;
        { float a = fabsf(ptop - q.y); if (a < dqm) { dqm = a; lq = 1; } }
        { float a = fabsf(ptop - q.z); if (a < dqm) { dqm = a; lq = 2; } }
        { float a = fabsf(ptop - q.w); if (a < dqm) { dqm = a; lq = 3; } }

        // lp / dp_min: which of NEIGHBOR layers is closest to own top depth
        float dpm = fabsf(q0 - pq.x); int lp = 0;
        { float a = fabsf(q0 - pq.y); if (a < dpm) { dpm = a; lp = 1; } }
        { float a = fabsf(q0 - pq.z); if (a < dpm) { dpm = a; lp = 2; } }
        { float a = fabsf(q0 - pq.w); if (a < dpm) { dpm = a; lp = 3; } }

        const int occ = (dqm <= dpm) ? lq : -lp;

#pragma unroll
        for (int kk = 0; kk < cfg::KK; ++kk) {
            const float4 A = g_A[kk][spix];
            const float4 B = g_B[kk][spix];
            const float fyv = (dy == -1) ? B.x : ((dy == 0) ? B.y : B.z);
            const float fxv = (dx == -1) ? A.w : ((dx == 0) ? B.w : g_C[kk][spix]);
            const float w = fyv * fxv;
            const int lvl = kk + occ;
            if (lvl < 0) {
                accF[0] = fmaf(A.x, w, accF[0]);
                accF[1] = fmaf(A.y, w, accF[1]);
                accF[2] = fmaf(A.z, w, accF[2]);
                accF[3] += w;
            } else if (lvl == 0) {
                accS[0] = fmaf(A.x, w, accS[0]);
                accS[1] = fmaf(A.y, w, accS[1]);
                accS[2] = fmaf(A.z, w, accS[2]);
                accS[3] += w;
            } else {
                accB[0] = fmaf(A.x, w, accB[0]);
                accB[1] = fmaf(A.y, w, accB[1]);
                accB[2] = fmaf(A.z, w, accB[2]);
                accB[3] += w;
            }
        }
    }

    // normalize each bucket (alpha channel == weight channel algebraically)
    const float ib = 1.0f / fmaxf(accB[3], 1e-10f);
    float o0 = accB[0] * ib, o1 = accB[1] * ib, o2 = accB[2] * ib, o3 = accB[3] * ib;

    const float is = 1.0f / fmaxf(accS[3], 1e-10f);
    {
        const float s0 = accS[0]*is, s1 = accS[1]*is, s2 = accS[2]*is, s3 = accS[3]*is;
        const float om = 1.0f - s3;
        o0 = s0 + om * o0; o1 = s1 + om * o1; o2 = s2 + om * o2; o3 = s3 + om * o3;
    }
    const float iff = 1.0f / fmaxf(accF[3], 1e-10f);
    {
        const float f0 = accF[0]*iff, f1 = accF[1]*iff, f2 = accF[2]*iff, f3 = accF[3]*iff;
        const float om = 1.0f - f3;
        o0 = f0 + om * o0; o1 = f1 + om * o1; o2 = f2 + om * o2; o3 = f3 + om * o3;
    }

    const float bgm = 1.0f - o3;
    reinterpret_cast<float4*>(out)[pix] =
        make_float4(o0 + bgm, o1 + bgm, o2 + bgm, o3);
}

// ---------------------------------------------------------------------------
extern "C" void kernel_launch(void* const* d_in, const int* in_sizes, int n_in,
                              void* d_out, int out_size)
{
    const float* texels  = (const float*)d_in[0];
    const float* normals = (const float*)d_in[1];
    const float* pcam    = (const float*)d_in[2];
    const float* screen  = (const float*)d_in[3];
    const float* qdepth  = (const float*)d_in[4];
    const void*  mask    = d_in[5];
    const float* Lp      = (const float*)d_in[6];
    const float* la      = (const float*)d_in[7];
    const float* ld      = (const float*)d_in[8];
    const float* ls      = (const float*)d_in[9];
    const float* Cp      = (const float*)d_in[10];
    const float* ma      = (const float*)d_in[11];
    const float* md      = (const float*)d_in[12];
    const float* ms      = (const float*)d_in[13];
    float* out = (float*)d_out;

    detect_kernel<<<1, 1024>>>((const uint4*)mask);

    shade_kernel<<<cfg::NE / 256, 256>>>(texels, normals, pcam, screen, mask,
                                         Lp, la, ld, ls, Cp, ma, md, ms);

    dim3 blk(32, 8, 1);
    dim3 grd(cfg::WW / 32, cfg::HH / 8, cfg::NB);
    blend_kernel<<<grd, blk>>>(qdepth, out);
}

// round 3
// speedup vs baseline: 1.8422x; 1.1167x over previous
#include <cuda_runtime.h>
#include <cuda_fp16.h>

// ---------------------------------------------------------------------------
// SplatterPhongShader: N=4, H=256, W=256, K=4
// Pass 1: Phong shade + separable splat factors -> scratch (24B/element:
//         fp32 rgb + fp16 gaussian factors; fp16 weight error cancels to
//         first order in the bucket ratio sum(rgb*w)/sum(w)).
// Pass 2: 3x3 gather with depth-occlusion bucketing + compositing.
// Scratch is SoA over the K (layer) dim for fully coalesced blend loads.
// ---------------------------------------------------------------------------

namespace cfg {
constexpr int NB = 4, HH = 256, WW = 256, KK = 4;
constexpr int NE   = NB * HH * WW * KK;   // 1,048,576 source elements
constexpr int NPIX = NB * HH * WW;        // 262,144 pixels
// (1+0.05) / (1 + 4*exp(-2) + 4*exp(-4))
constexpr float NORM_C = 0.6503143832f;
}

// Scratch, SoA by layer: [kk][pix]
__device__ float4 g_P[cfg::KK][cfg::NPIX];  // rgb0, rgb1, rgb2, half2(fy0,fy1)
__device__ uint2  g_Q[cfg::KK][cfg::NPIX];  // half2(fy2,fx0), half2(fx1,fx2)
__device__ int    g_mask_kind;              // 0=word (int32/float32), 2=byte/bool

static __device__ __forceinline__ unsigned pack2(float a, float b) {
    __half2 h = __floats2half2_rn(a, b);
    return *reinterpret_cast<unsigned*>(&h);
}
static __device__ __forceinline__ float lo_h(unsigned u) {
    return __half2float(__ushort_as_half((unsigned short)(u & 0xffffu)));
}
static __device__ __forceinline__ float hi_h(unsigned u) {
    return __half2float(__ushort_as_half((unsigned short)(u >> 16)));
}

// ---------------------------------------------------------------------------
// Mask dtype probe. int32 and float32 masks both satisfy "alpha = word != 0",
// so we only need to distinguish word-per-element vs byte-per-element (bool).
// A bool mask's nonzero words (cumsum-monotone bytes, little-endian) are
// always > 1 (0x01000000 / 0x01010101 ...), and a float mask's nonzero word
// is 0x3f800000 > 1, while an int mask only has words 0/1. So: any word > 1
// that is not 0x3f800000 => byte layout; any word == 1 => word layout;
// presence of 0x3f800000 => word layout. Scan 1024 words (4 KB) —
// P(ambiguous) is negligible for this data distribution.
// ---------------------------------------------------------------------------
__global__ __launch_bounds__(256)
void detect_kernel(const uint4* __restrict__ mw) {
    __shared__ unsigned int sflag[2];  // [0]: saw word>1 (not 0x3f800000), [1]: saw word==1 or 0x3f800000
    if (threadIdx.x == 0) { sflag[0] = 0u; sflag[1] = 0u; }
    __syncthreads();
    unsigned int sawbyte = 0u, sawword = 0u;
    uint4 v = mw[threadIdx.x];
    const unsigned int ws[4] = {v.x, v.y, v.z, v.w};
#pragma unroll
    for (int t = 0; t < 4; ++t) {
        unsigned int w = ws[t];
        if (w == 1u || w == 0x3f800000u) sawword = 1u;
        else if (w > 1u) sawbyte = 1u;
    }
    sawbyte = __ballot_sync(0xffffffffu, sawbyte);
    sawword = __ballot_sync(0xffffffffu, sawword);
    if ((threadIdx.x & 31) == 0) {
        if (sawbyte) atomicOr(&sflag[0], 1u);
        if (sawword) atomicOr(&sflag[1], 1u);
    }
    __syncthreads();
    if (threadIdx.x == 0)
        g_mask_kind = (sflag[0] && !sflag[1]) ? 2 : 0;
}

// ---------------------------------------------------------------------------
// Pass 1: Phong shading + separable gaussian factors
// ---------------------------------------------------------------------------
__global__ __launch_bounds__(256)
void shade_kernel(const float* __restrict__ texels,
                  const float* __restrict__ normals,
                  const float* __restrict__ pcam,
                  const float* __restrict__ screen,
                  const void*  __restrict__ mask,
                  const float* __restrict__ Lp,
                  const float* __restrict__ la,
                  const float* __restrict__ ld,
                  const float* __restrict__ ls,
                  const float* __restrict__ Cp,
                  const float* __restrict__ ma,
                  const float* __restrict__ md,
                  const float* __restrict__ ms)
{
    const int e = blockIdx.x * blockDim.x + threadIdx.x;
    if (e >= cfg::NE) return;

    const int pix = e >> 2;
    const int kk  = e & 3;
    const int x = (e >> 2)  & 255;
    const int y = (e >> 10) & 255;

    // ---- mask -> alpha (exact 0/1) ----
    bool m;
    if (g_mask_kind == 0) m = (((const unsigned int*)mask)[e] != 0u);
    else                  m = (((const unsigned char*)mask)[e] != 0);
    const float alpha = m ? 0.0f : 1.0f;

    // ---- Phong ----
    const float t0 = texels[3*e+0], t1 = texels[3*e+1], t2 = texels[3*e+2];
    float nx = normals[3*e+0], ny = normals[3*e+1], nz = normals[3*e+2];
    const float px = pcam[3*e+0], py = pcam[3*e+1], pz = pcam[3*e+2];

    float rin = rsqrtf(nx*nx + ny*ny + nz*nz + 1e-8f);
    nx *= rin; ny *= rin; nz *= rin;

    float lx = Lp[0] - px, ly = Lp[1] - py, lz = Lp[2] - pz;
    float ril = rsqrtf(lx*lx + ly*ly + lz*lz + 1e-8f);
    lx *= ril; ly *= ril; lz *= ril;

    float vx = Cp[0] - px, vy = Cp[1] - py, vz = Cp[2] - pz;
    float riv = rsqrtf(vx*vx + vy*vy + vz*vz + 1e-8f);
    vx *= riv; vy *= riv; vz *= riv;

    const float ndl = nx*lx + ny*ly + nz*lz;
    const float two_ndl = 2.0f * ndl;
    const float rx = two_ndl*nx - lx;
    const float ry = two_ndl*ny - ly;
    const float rz = two_ndl*nz - lz;
    float rdv = fmaxf(rx*vx + ry*vy + rz*vz, 0.0f);

    // rdv^64 by repeated squaring
    float s = rdv*rdv;  s = s*s;  s = s*s;  s = s*s;  s = s*s;  s = s*s;

    const float relndl = fmaxf(ndl, 0.0f);
    const float rgb0 = t0 * (la[0]*ma[0] + ld[0]*md[0]*relndl) + ls[0]*ms[0]*s;
    const float rgb1 = t1 * (la[1]*ma[1] + ld[1]*md[1]*relndl) + ls[1]*ms[1]*s;
    const float rgb2 = t2 * (la[2]*ma[2] + ld[2]*md[2]*relndl) + ls[2]*ms[2]*s;

    // ---- separable gaussian splat factors (2*sigma^2 = 0.5 -> coeff 2.0) ----
    const float jy = screen[2*e+0] - ((float)y + 0.5f);
    const float jx = screen[2*e+1] - ((float)x + 0.5f);
    const float na = cfg::NORM_C * alpha;

    const float fy0 = __expf(-2.0f * (jy + 1.0f) * (jy + 1.0f)) * na;
    const float fy1 = __expf(-2.0f *  jy         *  jy        ) * na;
    const float fy2 = __expf(-2.0f * (jy - 1.0f) * (jy - 1.0f)) * na;
    const float fx0 = __expf(-2.0f * (jx + 1.0f) * (jx + 1.0f));
    const float fx1 = __expf(-2.0f *  jx         *  jx        );
    const float fx2 = __expf(-2.0f * (jx - 1.0f) * (jx - 1.0f));

    g_P[kk][pix] = make_float4(rgb0, rgb1, rgb2,
                               __uint_as_float(pack2(fy0, fy1)));
    g_Q[kk][pix] = make_uint2(pack2(fy2, fx0), pack2(fx1, fx2));
}

// ---------------------------------------------------------------------------
// Pass 2: gather 3x3 neighborhood, depth-occlusion bucketing, composite
// ---------------------------------------------------------------------------
__global__ __launch_bounds__(256)
void blend_kernel(const float* __restrict__ qdepth, float* __restrict__ out)
{
    const int x = blockIdx.x * 32 + threadIdx.x;
    const int y = blockIdx.y * blockDim.y + threadIdx.y;
    const int n = blockIdx.z;
    const int pix = (n * cfg::HH + y) * cfg::WW + x;

    const float4* __restrict__ q4 = reinterpret_cast<const float4*>(qdepth);
    const float4 q = q4[pix];
    const float q0 = q.x;

    float accF[4] = {0.f, 0.f, 0.f, 0.f};   // level < 0  (foreground)
    float accS[4] = {0.f, 0.f, 0.f, 0.f};   // level == 0 (surface)
    float accB[4] = {0.f, 0.f, 0.f, 0.f};   // level > 0  (background)

#pragma unroll
    for (int d = 0; d < 9; ++d) {
        const int dy = d / 3 - 1;
        const int dx = d % 3 - 1;
        const int sy = y - dy;
        const int sx = x - dx;
        if ((unsigned)sy >= (unsigned)cfg::HH || (unsigned)sx >= (unsigned)cfg::WW)
            continue;
        const int spix = (n * cfg::HH + sy) * cfg::WW + sx;
        const float4 pq = q4[spix];
        const float ptop = pq.x;

        // lq / dq_min: which of OWN layers is closest to neighbor's top depth
        float dqm = fabsf(ptop - q.x); int lq = 0;
        { float a = fabsf(ptop - q.y); if (a < dqm) { dqm = a; lq = 1; } }
        { float a = fabsf(ptop - q.z); if (a < dqm) { dqm = a; lq = 2; } }
        { float a = fabsf(ptop - q.w); if (a < dqm) { dqm = a; lq = 3; } }

        // lp / dp_min: which of NEIGHBOR layers is closest to own top depth
        float dpm = fabsf(q0 - pq.x); int lp = 0;
        { float a = fabsf(q0 - pq.y); if (a < dpm) { dpm = a; lp = 1; } }
        { float a = fabsf(q0 - pq.z); if (a < dpm) { dpm = a; lp = 2; } }
        { float a = fabsf(q0 - pq.w); if (a < dpm) { dpm = a; lp = 3; } }

        const int occ = (dqm <= dpm) ? lq : -lp;

#pragma unroll
        for (int kk = 0; kk < cfg::KK; ++kk) {
            const float4 P = g_P[kk][spix];
            const uint2  Qv = g_Q[kk][spix];
            const unsigned u01 = __float_as_uint(P.w);  // fy0, fy1
            // fy select (compile-time per d)
            const float fyv = (dy == -1) ? lo_h(u01)
                            : (dy ==  0) ? hi_h(u01)
                                         : lo_h(Qv.x);  // fy2
            const float fxv = (dx == -1) ? hi_h(Qv.x)   // fx0
                            : (dx ==  0) ? lo_h(Qv.y)   // fx1
                                         : hi_h(Qv.y);  // fx2
            const float w = fyv * fxv;
            const int lvl = kk + occ;
            if (lvl < 0) {
                accF[0] = fmaf(P.x, w, accF[0]);
                accF[1] = fmaf(P.y, w, accF[1]);
                accF[2] = fmaf(P.z, w, accF[2]);
                accF[3] += w;
            } else if (lvl == 0) {
                accS[0] = fmaf(P.x, w, accS[0]);
                accS[1] = fmaf(P.y, w, accS[1]);
                accS[2] = fmaf(P.z, w, accS[2]);
                accS[3] += w;
            } else {
                accB[0] = fmaf(P.x, w, accB[0]);
                accB[1] = fmaf(P.y, w, accB[1]);
                accB[2] = fmaf(P.z, w, accB[2]);
                accB[3] += w;
            }
        }
    }

    // normalize each bucket (alpha channel == weight channel algebraically)
    const float ib = 1.0f / fmaxf(accB[3], 1e-10f);
    float o0 = accB[0] * ib, o1 = accB[1] * ib, o2 = accB[2] * ib, o3 = accB[3] * ib;

    const float is = 1.0f / fmaxf(accS[3], 1e-10f);
    {
        const float s0 = accS[0]*is, s1 = accS[1]*is, s2 = accS[2]*is, s3 = accS[3]*is;
        const float om = 1.0f - s3;
        o0 = s0 + om * o0; o1 = s1 + om * o1; o2 = s2 + om * o2; o3 = s3 + om * o3;
    }
    const float iff = 1.0f / fmaxf(accF[3], 1e-10f);
    {
        const float f0 = accF[0]*iff, f1 = accF[1]*iff, f2 = accF[2]*iff, f3 = accF[3]*iff;
        const float om = 1.0f - f3;
        o0 = f0 + om * o0; o1 = f1 + om * o1; o2 = f2 + om * o2; o3 = f3 + om * o3;
    }

    const float bgm = 1.0f - o3;
    reinterpret_cast<float4*>(out)[pix] =
        make_float4(o0 + bgm, o1 + bgm, o2 + bgm, o3);
}

// ---------------------------------------------------------------------------
extern "C" void kernel_launch(void* const* d_in, const int* in_sizes, int n_in,
                              void* d_out, int out_size)
{
    const float* texels  = (const float*)d_in[0];
    const float* normals = (const float*)d_in[1];
    const float* pcam    = (const float*)d_in[2];
    const float* screen  = (const float*)d_in[3];
    const float* qdepth  = (const float*)d_in[4];
    const void*  mask    = d_in[5];
    const float* Lp      = (const float*)d_in[6];
    const float* la      = (const float*)d_in[7];
    const float* ld      = (const float*)d_in[8];
    const float* ls      = (const float*)d_in[9];
    const float* Cp      = (const float*)d_in[10];
    const float* ma      = (const float*)d_in[11];
    const float* md      = (const float*)d_in[12];
    const float* ms      = (const float*)d_in[13];
    float* out = (float*)d_out;

    detect_kernel<<<1, 256>>>((const uint4*)mask);

    shade_kernel<<<cfg::NE / 256, 256>>>(texels, normals, pcam, screen, mask,
                                         Lp, la, ld, ls, Cp, ma, md, ms);

    dim3 blk(32, 8, 1);
    dim3 grd(cfg::WW / 32, cfg::HH / 8, cfg::NB);
    blend_kernel<<<grd, blk>>>(qdepth, out);
}